// round 8
// baseline (speedup 1.0000x reference)
#include <cuda_runtime.h>
#include <cuda_fp16.h>
#include <cstdint>

#define DIM 128
#define NL 4

// ---------------------------------------------------------------------------
// Device scratch (no allocations allowed)
// ---------------------------------------------------------------------------
__device__ float g_Ur[DIM * DIM];    // U[t][j]   (row t, col j)
__device__ float g_Ui[DIM * DIM];
__device__ float g_UrT[DIM * DIM];   // U^T[j][t]
__device__ float g_UiT[DIM * DIM];
// Pre-swizzled fp16 smem image of A (B^T operand), [n=128][k=128], 256B pitch.
__device__ __align__(16) unsigned char g_Aimg[DIM * DIM * 2];  // 32 KB

// ---------------------------------------------------------------------------
// Helpers
// ---------------------------------------------------------------------------
__device__ __forceinline__ uint32_t smem_u32(const void* p) {
    uint32_t a;
    asm("{ .reg .u64 t; cvta.to.shared.u64 t, %1; cvt.u32.u64 %0, t; }"
        : "=r"(a) : "l"(p));
    return a;
}
__device__ __forceinline__ void ldsm_x4(uint32_t* r, uint32_t addr) {
    asm volatile("ldmatrix.sync.aligned.m8n8.x4.shared.b16 {%0,%1,%2,%3}, [%4];"
                 : "=r"(r[0]), "=r"(r[1]), "=r"(r[2]), "=r"(r[3]) : "r"(addr));
}
__device__ __forceinline__ void mma16816(float* d, const uint32_t* a,
                                         const uint32_t* b) {
    asm volatile(
        "mma.sync.aligned.m16n8k16.row.col.f32.f16.f16.f32 "
        "{%0,%1,%2,%3}, {%4,%5,%6,%7}, {%8,%9}, {%0,%1,%2,%3};"
        : "+f"(d[0]), "+f"(d[1]), "+f"(d[2]), "+f"(d[3])
        : "r"(a[0]), "r"(a[1]), "r"(a[2]), "r"(a[3]), "r"(b[0]), "r"(b[1]));
}

// ---------------------------------------------------------------------------
// Prep 1: build U columns.  One warp per column; state in registers.
// CNOT permutation via smem (1 dependent level) instead of 8-shfl gather.
// qubit w <-> bit (6-w) of the linear index.
// ---------------------------------------------------------------------------
__global__ __launch_bounds__(32)
void build_u_kernel(const float* __restrict__ w) {
    __shared__ float gc[28][8];
    __shared__ float tr[DIM], ti[DIM];
    const int L = threadIdx.x;
    const int j = blockIdx.x;
    const unsigned FULL = 0xffffffffu;

    if (L < 28) {
        const float phi = w[L * 3 + 0], th = w[L * 3 + 1], om = w[L * 3 + 2];
        float s, c;   __sincosf(0.5f * th, &s, &c);
        float sa, ca; __sincosf(0.5f * (phi + om), &sa, &ca);
        float sb, cb; __sincosf(0.5f * (phi - om), &sb, &cb);
        gc[L][0] =  ca * c; gc[L][1] = -sa * c;   // u00
        gc[L][2] = -cb * s; gc[L][3] = -sb * s;   // u01
        gc[L][4] =  cb * s; gc[L][5] = -sb * s;   // u10
        gc[L][6] =  ca * c; gc[L][7] =  sa * c;   // u11
    }
    float sr[4], si[4];
    #pragma unroll
    for (int m = 0; m < 4; m++) {
        const int t = (m << 5) | L;
        sr[m] = (t == j) ? 1.0f : 0.0f;
        si[m] = 0.0f;
    }
    __syncwarp();

    for (int l = 0; l < NL; l++) {               // NOT unrolled (I-footprint)
        #pragma unroll
        for (int q = 0; q < 7; q++) {
            const int g = l * 7 + q;
            const float u00r = gc[g][0], u00i = gc[g][1];
            const float u01r = gc[g][2], u01i = gc[g][3];
            const float u10r = gc[g][4], u10i = gc[g][5];
            const float u11r = gc[g][6], u11i = gc[g][7];
            if (q >= 2) {
                const int mask = 1 << (6 - q);
                const bool hi = (L & mask) != 0;
                const float c0r = hi ? u10r : u00r, c0i = hi ? u10i : u00i;
                const float c1r = hi ? u11r : u01r, c1i = hi ? u11i : u01i;
                #pragma unroll
                for (int m = 0; m < 4; m++) {
                    const float pr = __shfl_xor_sync(FULL, sr[m], mask);
                    const float pi = __shfl_xor_sync(FULL, si[m], mask);
                    const float a0r = hi ? pr : sr[m], a0i = hi ? pi : si[m];
                    const float a1r = hi ? sr[m] : pr, a1i = hi ? si[m] : pi;
                    sr[m] = c0r * a0r - c0i * a0i + c1r * a1r - c1i * a1i;
                    si[m] = c0r * a0i + c0i * a0r + c1r * a1i + c1i * a1r;
                }
            } else {
                const int d = (q == 0) ? 2 : 1;
                #pragma unroll
                for (int m = 0; m < 4; m++) {
                    if (!(m & d)) {
                        const int mh = m | d;
                        const float a0r = sr[m],  a0i = si[m];
                        const float a1r = sr[mh], a1i = si[mh];
                        sr[m]  = u00r * a0r - u00i * a0i + u01r * a1r - u01i * a1i;
                        si[m]  = u00r * a0i + u00i * a0r + u01r * a1i + u01i * a1r;
                        sr[mh] = u10r * a0r - u10i * a0i + u11r * a1r - u11i * a1i;
                        si[mh] = u10r * a0i + u10i * a0r + u11r * a1i + u11i * a1r;
                    }
                }
            }
        }
        // fused CNOT layer via smem permute: new[t] = old[s(t)]
        const int r = (l % 6) + 1;
        #pragma unroll
        for (int m = 0; m < 4; m++) {
            const int t = (m << 5) | L;
            tr[t] = sr[m]; ti[t] = si[m];
        }
        __syncwarp();
        #pragma unroll
        for (int m = 0; m < 4; m++) {
            int s = (m << 5) | L;
            #pragma unroll
            for (int qq = 6; qq >= 0; qq--) {
                const int cb = 1 << (6 - qq);
                const int tb = 1 << (6 - ((qq + r) % 7));
                if (s & cb) s ^= tb;
            }
            sr[m] = tr[s]; si[m] = ti[s];
        }
        __syncwarp();
    }
    #pragma unroll
    for (int m = 0; m < 4; m++) {
        const int t = (m << 5) | L;
        g_Ur[t * DIM + j]  = sr[m];
        g_Ui[t * DIM + j]  = si[m];
        g_UrT[j * DIM + t] = sr[m];
        g_UiT[j * DIM + t] = si[m];
    }
    cudaTriggerProgrammaticLaunchCompletion();
}

// ---------------------------------------------------------------------------
// Prep 2: A[i][j] = sum_k sgn(k)(Ur[k][i]Ur[k][j]+Ui[k][i]Ui[k][j]);
// 256 threads: k split in two halves, combined via smem.
// ---------------------------------------------------------------------------
__global__ __launch_bounds__(256)
void build_a_kernel() {
    __shared__ float cr[DIM], ci[DIM], part[2][DIM];
    const int t = threadIdx.x;
    const int j = t & 127, h = t >> 7;
    const int i = blockIdx.x;

    cudaGridDependencySynchronize();   // wait for build_u grid

    if (h == 0) {
        const float sg = (__popc(j & 0x41) & 1) ? -1.0f : 1.0f;
        cr[j] = sg * g_UrT[i * DIM + j];   // = sgn(j) * Ur[j][i], coalesced
        ci[j] = sg * g_UiT[i * DIM + j];
    }
    __syncthreads();
    float acc = 0.0f;
    const int k0 = h * 64;
    #pragma unroll 8
    for (int k = k0; k < k0 + 64; k++)
        acc += cr[k] * g_Ur[k * DIM + j] + ci[k] * g_Ui[k * DIM + j];
    part[h][j] = acc;
    __syncthreads();
    if (h == 0) {
        const __half hi = __float2half_rn(part[0][j] + part[1][j]);
        const int chi = j >> 3, sel = i & 7, within = (j & 7) * 2;
        *(__half*)(g_Aimg + i * 256 + ((chi ^ sel) << 4) + within) = hi;
    }
    cudaTriggerProgrammaticLaunchCompletion();
}

// ---------------------------------------------------------------------------
// Main kernel: CTA = 256 threads (8 warps) / 128 batch rows.
// Warp (wm, wn): M=32 rows (wm*32), N=64 cols (wn*64), K=128.
// Software-pipelined mainloop: a/b fragments prefetched one step ahead.
// smem: A 32KB @0, Xs fp16 32KB @32768, norm partials (128x36 f32) @65536,
//       dot partials @83968.
// ---------------------------------------------------------------------------
#define AS_OFF   0
#define XS_OFF   32768
#define REDN_OFF 65536
#define PART_OFF 83968
#define SMEM_BYTES 84992

__global__ __launch_bounds__(256, 2)
void vqa_main(const float* __restrict__ X, float* __restrict__ out) {
    extern __shared__ __align__(16) unsigned char smem[];
    const uint32_t sb = smem_u32(smem);
    const int tid = threadIdx.x;
    const int w = tid >> 5, L = tid & 31;
    const int wm = w & 3, wn = w >> 2;
    const size_t row0 = (size_t)blockIdx.x * DIM;

    // ---- PRE-SYNC: load X, convert fp16 (swizzled), per-lane norm partials ----
    {
        float* redn = (float*)(smem + REDN_OFF);
        const float4* Xg = (const float4*)(X + row0 * DIM);
        #pragma unroll
        for (int i = 0; i < 16; i++) {
            const float4 v = Xg[i * 256 + tid];
            const int row = i * 8 + w;       // warp-uniform row
            const int c4 = L;                // float4 index within row (0..31)
            const __half2 h01 = __floats2half2_rn(v.x, v.y);
            const __half2 h23 = __floats2half2_rn(v.z, v.w);
            struct __align__(8) H4 { __half2 a, b; };
            const int byte = XS_OFF + row * 256 +
                             (((c4 >> 1) ^ (row & 7)) << 4) + ((c4 & 1) << 3);
            *(H4*)(smem + byte) = H4{h01, h23};
            redn[row * 36 + L] = v.x * v.x + v.y * v.y + v.z * v.z + v.w * v.w;
        }
    }

    cudaGridDependencySynchronize();   // wait for build_a grid (A ready)

    // ---- copy pre-swizzled A image (32KB) ----
    {
        const uint4* Ag = (const uint4*)g_Aimg;
        uint4* Asv = (uint4*)(smem + AS_OFF);
        #pragma unroll
        for (int i = 0; i < 8; i++) Asv[i * 256 + tid] = Ag[i * 256 + tid];
    }
    __syncthreads();

    // ---- GEMM: warp computes D[32 x 64] over K=128, pipelined ----
    float d[8][2][4];
    #pragma unroll
    for (int n = 0; n < 8; n++)
        #pragma unroll
        for (int m = 0; m < 2; m++)
            #pragma unroll
            for (int e = 0; e < 4; e++) d[n][m][e] = 0.0f;

    const int m0 = wm * 32;
    const int n0 = wn * 64;
    const int ra0 = m0 + (L & 15);
    const int ra1 = ra0 + 16;
    const int bnr = ((L >> 4) << 3) + (L & 7);
    const int bh = (L >> 3) & 1;

    const uint32_t aB0 = sb + XS_OFF + ra0 * 256;
    const uint32_t aB1 = sb + XS_OFF + ra1 * 256;
    const int asel0 = (ra0 & 7), asel1 = (ra1 & 7);
    // B row bases + swizzle selectors for the 4 n2-groups (k-independent)
    uint32_t brow[4]; int bsel[4];
    #pragma unroll
    for (int n2 = 0; n2 < 4; n2++) {
        const int nr = n0 + n2 * 16 + bnr;
        brow[n2] = sb + AS_OFF + nr * 256;
        bsel[n2] = nr & 7;
    }
    const int ak = (L >> 4);   // a-frag k8-half

    uint32_t a0c[4], a1c[4], a0n[4], a1n[4], bc[4], bn[4];
    ldsm_x4(a0c, aB0 + (((0 + ak) ^ asel0) << 4));
    ldsm_x4(a1c, aB1 + (((0 + ak) ^ asel1) << 4));
    ldsm_x4(bc, brow[0] + (((0 + bh) ^ bsel[0]) << 4));

    #pragma unroll
    for (int k = 0; k < 8; k++) {
        const int kn = (k < 7) ? k + 1 : 7;
        ldsm_x4(a0n, aB0 + (((2 * kn + ak) ^ asel0) << 4));
        ldsm_x4(a1n, aB1 + (((2 * kn + ak) ^ asel1) << 4));
        #pragma unroll
        for (int n2 = 0; n2 < 4; n2++) {
            // prefetch next b: (k, n2+1) or (k+1, 0)
            const int pn2 = (n2 + 1) & 3;
            const int pk = (n2 < 3) ? k : kn;
            ldsm_x4(bn, brow[pn2] + (((2 * pk + bh) ^ bsel[pn2]) << 4));
            mma16816(d[2 * n2][0],     a0c, bc);
            mma16816(d[2 * n2][1],     a1c, bc);
            mma16816(d[2 * n2 + 1][0], a0c, bc + 2);
            mma16816(d[2 * n2 + 1][1], a1c, bc + 2);
            #pragma unroll
            for (int e = 0; e < 4; e++) bc[e] = bn[e];
        }
        #pragma unroll
        for (int e = 0; e < 4; e++) { a0c[e] = a0n[e]; a1c[e] = a1n[e]; }
    }

    // ---- epilogue: partial dot over this warp's 64 cols ----
    const int q = L & 3, rq = L >> 2;
    float acc[4] = {0.f, 0.f, 0.f, 0.f};
    int rows[4];
    #pragma unroll
    for (int h = 0; h < 4; h++) rows[h] = m0 + (h >> 1) * 16 + (h & 1) * 8 + rq;

    #pragma unroll
    for (int nl = 0; nl < 8; nl++) {
        const int chunk = wn * 8 + nl;
        #pragma unroll
        for (int h = 0; h < 4; h++) {
            const int row = rows[h];
            const int byte = XS_OFF + row * 256 +
                             ((chunk ^ (row & 7)) << 4) + (q << 2);
            const float2 xf = __half22float2(*(const __half2*)(smem + byte));
            const int mt = h >> 1, pr = (h & 1) * 2;
            acc[h] += xf.x * d[nl][mt][pr] + xf.y * d[nl][mt][pr + 1];
        }
    }
    #pragma unroll
    for (int h = 0; h < 4; h++) {
        acc[h] += __shfl_xor_sync(0xffffffffu, acc[h], 1);
        acc[h] += __shfl_xor_sync(0xffffffffu, acc[h], 2);
    }
    float* redp = (float*)(smem + PART_OFF);
    if (q == 0) {
        #pragma unroll
        for (int h = 0; h < 4; h++) redp[rows[h] * 2 + wn] = acc[h];
    }
    __syncthreads();

    if (tid < DIM) {
        float nrm = 0.0f;
        const float4* rn = (const float4*)(smem + REDN_OFF + tid * 144);
        #pragma unroll
        for (int c = 0; c < 8; c++) {
            const float4 p4 = rn[c];
            nrm += p4.x + p4.y + p4.z + p4.w;
        }
        out[row0 + tid] = (redp[tid * 2] + redp[tid * 2 + 1]) / nrm;
    }
}

// ---------------------------------------------------------------------------
extern "C" void kernel_launch(void* const* d_in, const int* in_sizes, int n_in,
                              void* d_out, int out_size) {
    const float* x = (const float*)d_in[0];
    const float* w = (const float*)d_in[1];
    int xi = 0;
    if (n_in >= 2 && in_sizes[0] == NL * 7 * 3) {
        x = (const float*)d_in[1];
        w = (const float*)d_in[0];
        xi = 1;
    }
    const int batch = in_sizes[xi] / DIM;
    float* outp = (float*)d_out;

    cudaFuncSetAttribute(vqa_main, cudaFuncAttributeMaxDynamicSharedMemorySize,
                         SMEM_BYTES);

    cudaLaunchAttribute at;
    at.id = cudaLaunchAttributeProgrammaticStreamSerialization;
    at.val.programmaticStreamSerializationAllowed = 1;

    build_u_kernel<<<DIM, 32>>>(w);

    {
        cudaLaunchConfig_t cfg = {};
        cfg.gridDim = dim3(DIM);
        cfg.blockDim = dim3(256);
        cfg.attrs = &at;
        cfg.numAttrs = 1;
        if (cudaLaunchKernelEx(&cfg, build_a_kernel) != cudaSuccess)
            build_a_kernel<<<DIM, 256>>>();
    }
    {
        cudaLaunchConfig_t cfg = {};
        cfg.gridDim = dim3(batch / DIM);
        cfg.blockDim = dim3(256);
        cfg.dynamicSmemBytes = SMEM_BYTES;
        cfg.attrs = &at;
        cfg.numAttrs = 1;
        if (cudaLaunchKernelEx(&cfg, vqa_main, x, outp) != cudaSuccess)
            vqa_main<<<batch / DIM, 256, SMEM_BYTES>>>(x, outp);
    }
}

// round 9
// speedup vs baseline: 1.1238x; 1.1238x over previous
#include <cuda_runtime.h>
#include <cuda_fp16.h>
#include <cstdint>

#define DIM 128
#define NL 4

// ---------------------------------------------------------------------------
// Device scratch (no allocations allowed)
// ---------------------------------------------------------------------------
__device__ float g_Ur[DIM * DIM];    // U[t][j]   (row t, col j)
__device__ float g_Ui[DIM * DIM];
__device__ float g_UrT[DIM * DIM];   // U^T[j][t]
__device__ float g_UiT[DIM * DIM];
// Pre-swizzled fp16 smem image of A (B^T operand), [n=128][k=128], 256B pitch.
__device__ __align__(16) unsigned char g_Aimg[DIM * DIM * 2];  // 32 KB

// ---------------------------------------------------------------------------
// Helpers
// ---------------------------------------------------------------------------
__device__ __forceinline__ uint32_t smem_u32(const void* p) {
    uint32_t a;
    asm("{ .reg .u64 t; cvta.to.shared.u64 t, %1; cvt.u32.u64 %0, t; }"
        : "=r"(a) : "l"(p));
    return a;
}
__device__ __forceinline__ void ldsm_x4(uint32_t* r, uint32_t addr) {
    asm volatile("ldmatrix.sync.aligned.m8n8.x4.shared.b16 {%0,%1,%2,%3}, [%4];"
                 : "=r"(r[0]), "=r"(r[1]), "=r"(r[2]), "=r"(r[3]) : "r"(addr));
}
__device__ __forceinline__ void mma16816(float* d, const uint32_t* a,
                                         const uint32_t* b) {
    asm volatile(
        "mma.sync.aligned.m16n8k16.row.col.f32.f16.f16.f32 "
        "{%0,%1,%2,%3}, {%4,%5,%6,%7}, {%8,%9}, {%0,%1,%2,%3};"
        : "+f"(d[0]), "+f"(d[1]), "+f"(d[2]), "+f"(d[3])
        : "r"(a[0]), "r"(a[1]), "r"(a[2]), "r"(a[3]), "r"(b[0]), "r"(b[1]));
}

// ---------------------------------------------------------------------------
// Prep 1: build U columns.  One warp per column; state in registers.
// qubit w <-> bit (6-w) of the linear index.
// ---------------------------------------------------------------------------
__global__ __launch_bounds__(32)
void build_u_kernel(const float* __restrict__ w) {
    __shared__ float gc[28][8];
    __shared__ float tr[DIM], ti[DIM];
    const int L = threadIdx.x;
    const int j = blockIdx.x;
    const unsigned FULL = 0xffffffffu;

    if (L < 28) {
        const float phi = w[L * 3 + 0], th = w[L * 3 + 1], om = w[L * 3 + 2];
        float s, c;   __sincosf(0.5f * th, &s, &c);
        float sa, ca; __sincosf(0.5f * (phi + om), &sa, &ca);
        float sb, cb; __sincosf(0.5f * (phi - om), &sb, &cb);
        gc[L][0] =  ca * c; gc[L][1] = -sa * c;   // u00
        gc[L][2] = -cb * s; gc[L][3] = -sb * s;   // u01
        gc[L][4] =  cb * s; gc[L][5] = -sb * s;   // u10
        gc[L][6] =  ca * c; gc[L][7] =  sa * c;   // u11
    }
    float sr[4], si[4];
    #pragma unroll
    for (int m = 0; m < 4; m++) {
        const int t = (m << 5) | L;
        sr[m] = (t == j) ? 1.0f : 0.0f;
        si[m] = 0.0f;
    }
    __syncwarp();

    for (int l = 0; l < NL; l++) {
        #pragma unroll
        for (int q = 0; q < 7; q++) {
            const int g = l * 7 + q;
            const float u00r = gc[g][0], u00i = gc[g][1];
            const float u01r = gc[g][2], u01i = gc[g][3];
            const float u10r = gc[g][4], u10i = gc[g][5];
            const float u11r = gc[g][6], u11i = gc[g][7];
            if (q >= 2) {
                const int mask = 1 << (6 - q);
                const bool hi = (L & mask) != 0;
                const float c0r = hi ? u10r : u00r, c0i = hi ? u10i : u00i;
                const float c1r = hi ? u11r : u01r, c1i = hi ? u11i : u01i;
                #pragma unroll
                for (int m = 0; m < 4; m++) {
                    const float pr = __shfl_xor_sync(FULL, sr[m], mask);
                    const float pi = __shfl_xor_sync(FULL, si[m], mask);
                    const float a0r = hi ? pr : sr[m], a0i = hi ? pi : si[m];
                    const float a1r = hi ? sr[m] : pr, a1i = hi ? si[m] : pi;
                    sr[m] = c0r * a0r - c0i * a0i + c1r * a1r - c1i * a1i;
                    si[m] = c0r * a0i + c0i * a0r + c1r * a1i + c1i * a1r;
                }
            } else {
                const int d = (q == 0) ? 2 : 1;
                #pragma unroll
                for (int m = 0; m < 4; m++) {
                    if (!(m & d)) {
                        const int mh = m | d;
                        const float a0r = sr[m],  a0i = si[m];
                        const float a1r = sr[mh], a1i = si[mh];
                        sr[m]  = u00r * a0r - u00i * a0i + u01r * a1r - u01i * a1i;
                        si[m]  = u00r * a0i + u00i * a0r + u01r * a1i + u01i * a1r;
                        sr[mh] = u10r * a0r - u10i * a0i + u11r * a1r - u11i * a1i;
                        si[mh] = u10r * a0i + u10i * a0r + u11r * a1i + u11i * a1r;
                    }
                }
            }
        }
        // fused CNOT layer via smem permute: new[t] = old[s(t)]
        const int r = (l % 6) + 1;
        #pragma unroll
        for (int m = 0; m < 4; m++) {
            const int t = (m << 5) | L;
            tr[t] = sr[m]; ti[t] = si[m];
        }
        __syncwarp();
        #pragma unroll
        for (int m = 0; m < 4; m++) {
            int s = (m << 5) | L;
            #pragma unroll
            for (int qq = 6; qq >= 0; qq--) {
                const int cb = 1 << (6 - qq);
                const int tb = 1 << (6 - ((qq + r) % 7));
                if (s & cb) s ^= tb;
            }
            sr[m] = tr[s]; si[m] = ti[s];
        }
        __syncwarp();
    }
    #pragma unroll
    for (int m = 0; m < 4; m++) {
        const int t = (m << 5) | L;
        g_Ur[t * DIM + j]  = sr[m];
        g_Ui[t * DIM + j]  = si[m];
        g_UrT[j * DIM + t] = sr[m];
        g_UiT[j * DIM + t] = si[m];
    }
    cudaTriggerProgrammaticLaunchCompletion();
}

// ---------------------------------------------------------------------------
// Prep 2: A[i][j] = sum_k sgn(k)(Ur[k][i]Ur[k][j]+Ui[k][i]Ui[k][j]);
// 256 threads: k split in two halves, combined via smem.
// ---------------------------------------------------------------------------
__global__ __launch_bounds__(256)
void build_a_kernel() {
    __shared__ float cr[DIM], ci[DIM], part[2][DIM];
    const int t = threadIdx.x;
    const int j = t & 127, h = t >> 7;
    const int i = blockIdx.x;

    cudaGridDependencySynchronize();   // wait for build_u grid

    if (h == 0) {
        const float sg = (__popc(j & 0x41) & 1) ? -1.0f : 1.0f;
        cr[j] = sg * g_UrT[i * DIM + j];   // = sgn(j) * Ur[j][i], coalesced
        ci[j] = sg * g_UiT[i * DIM + j];
    }
    __syncthreads();
    float acc = 0.0f;
    const int k0 = h * 64;
    #pragma unroll 8
    for (int k = k0; k < k0 + 64; k++)
        acc += cr[k] * g_Ur[k * DIM + j] + ci[k] * g_Ui[k * DIM + j];
    part[h][j] = acc;
    __syncthreads();
    if (h == 0) {
        const __half hi = __float2half_rn(part[0][j] + part[1][j]);
        const int chi = j >> 3, sel = i & 7, within = (j & 7) * 2;
        *(__half*)(g_Aimg + i * 256 + ((chi ^ sel) << 4) + within) = hi;
    }
    cudaTriggerProgrammaticLaunchCompletion();
}

// ---------------------------------------------------------------------------
// Main kernel: CTA = 256 threads (8 warps) / 128 batch rows.
// Warp = M=16 rows (w*16) x FULL N=128, K=128 -- fully independent after the
// single A-barrier: no cross-warp reduction, no norm staging, no final sync.
// Norm computed in-epilogue from the fp16 image (error ~2.5e-5, negligible).
// smem: A 32KB @0, Xs fp16 32KB @32768.  Total 64KB -> 2 CTAs/SM.
// ---------------------------------------------------------------------------
#define AS_OFF   0
#define XS_OFF   32768
#define SMEM_BYTES 65536

__global__ __launch_bounds__(256, 2)
void vqa_main(const float* __restrict__ X, float* __restrict__ out) {
    extern __shared__ __align__(16) unsigned char smem[];
    const uint32_t sb = smem_u32(smem);
    const int tid = threadIdx.x;
    const int w = tid >> 5, L = tid & 31;
    const size_t row0 = (size_t)blockIdx.x * DIM;
    const int r0w = w * 16;                 // warp's 16 rows

    // ---- PRE-SYNC: load warp's 16 rows of X, convert fp16 swizzled ----
    {
        const float4* Xg = (const float4*)(X + row0 * DIM);
        struct __align__(8) H4 { __half2 a, b; };
        const int sts_base = XS_OFF + (((L >> 1) ^ 0) << 4) + ((L & 1) << 3);
        #pragma unroll
        for (int i = 0; i < 16; i++) {
            const int row = r0w + i;
            const float4 v = Xg[row * 32 + L];
            const H4 hv = { __floats2half2_rn(v.x, v.y),
                            __floats2half2_rn(v.z, v.w) };
            const int byte = XS_OFF + row * 256 +
                             (((L >> 1) ^ (row & 7)) << 4) + ((L & 1) << 3);
            *(H4*)(smem + byte) = hv;
        }
        (void)sts_base;
    }

    cudaGridDependencySynchronize();   // wait for build_a grid (A ready)

    // ---- copy pre-swizzled A image (32KB) ----
    {
        const uint4* Ag = (const uint4*)g_Aimg;
        uint4* Asv = (uint4*)(smem + AS_OFF);
        #pragma unroll
        for (int i = 0; i < 8; i++) Asv[i * 256 + tid] = Ag[i * 256 + tid];
    }
    __syncthreads();   // the ONLY cta-wide barrier

    // ---- GEMM: warp computes D[16 x 128] over K=128 ----
    float d[16][4];
    #pragma unroll
    for (int n = 0; n < 16; n++)
        #pragma unroll
        for (int e = 0; e < 4; e++) d[n][e] = 0.0f;

    const int ra  = r0w + (L & 15);         // a-frag row (sel = L&7)
    const int sel = L & 7;                  // swizzle selector (a and b)
    const int ak  = L >> 4;                 // a k8-half
    const int bnr = ((L >> 4) << 3) + (L & 7);
    const int bh  = (L >> 3) & 1;           // b k8-half
    const uint32_t aBase = sb + XS_OFF + ra * 256;
    const uint32_t bBase = sb + AS_OFF + bnr * 256;

    #pragma unroll
    for (int k = 0; k < 8; k++) {
        uint32_t a[4];
        ldsm_x4(a, aBase + (((2 * k + ak) ^ sel) << 4));
        const uint32_t bx = ((2 * k + bh) ^ sel) << 4;
        #pragma unroll
        for (int n2 = 0; n2 < 8; n2++) {
            uint32_t b[4];
            ldsm_x4(b, bBase + n2 * 16 * 256 + bx);
            mma16816(d[2 * n2],     a, b);
            mma16816(d[2 * n2 + 1], a, b + 2);
        }
    }

    // ---- epilogue: per-row dot(x_hat, y) and ||x_hat||^2, all in-warp ----
    const int rA = r0w + (L >> 2);          // rows this lane reduces
    const int rB = rA + 8;
    float accA = 0.f, accB = 0.f, nrmA = 0.f, nrmB = 0.f;
    const uint32_t xaB = sb + XS_OFF + rA * 256 + ((L & 3) << 2);
    const uint32_t xbB = sb + XS_OFF + rB * 256 + ((L & 3) << 2);
    const int selA = rA & 7, selB = rB & 7;
    #pragma unroll
    for (int n = 0; n < 16; n++) {
        __half2 ha = *(const __half2*)(smem + (xaB - sb) + ((n ^ selA) << 4));
        __half2 hb = *(const __half2*)(smem + (xbB - sb) + ((n ^ selB) << 4));
        const float2 xa = __half22float2(ha);
        const float2 xb = __half22float2(hb);
        accA += xa.x * d[n][0] + xa.y * d[n][1];
        accB += xb.x * d[n][2] + xb.y * d[n][3];
        nrmA += xa.x * xa.x + xa.y * xa.y;
        nrmB += xb.x * xb.x + xb.y * xb.y;
    }
    #pragma unroll
    for (int o = 1; o <= 2; o <<= 1) {
        accA += __shfl_xor_sync(0xffffffffu, accA, o);
        accB += __shfl_xor_sync(0xffffffffu, accB, o);
        nrmA += __shfl_xor_sync(0xffffffffu, nrmA, o);
        nrmB += __shfl_xor_sync(0xffffffffu, nrmB, o);
    }
    if ((L & 3) == 0) {
        out[row0 + rA] = accA / nrmA;
        out[row0 + rB] = accB / nrmB;
    }
}

// ---------------------------------------------------------------------------
extern "C" void kernel_launch(void* const* d_in, const int* in_sizes, int n_in,
                              void* d_out, int out_size) {
    const float* x = (const float*)d_in[0];
    const float* w = (const float*)d_in[1];
    int xi = 0;
    if (n_in >= 2 && in_sizes[0] == NL * 7 * 3) {
        x = (const float*)d_in[1];
        w = (const float*)d_in[0];
        xi = 1;
    }
    const int batch = in_sizes[xi] / DIM;
    float* outp = (float*)d_out;

    cudaFuncSetAttribute(vqa_main, cudaFuncAttributeMaxDynamicSharedMemorySize,
                         SMEM_BYTES);

    cudaLaunchAttribute at;
    at.id = cudaLaunchAttributeProgrammaticStreamSerialization;
    at.val.programmaticStreamSerializationAllowed = 1;

    build_u_kernel<<<DIM, 32>>>(w);

    {
        cudaLaunchConfig_t cfg = {};
        cfg.gridDim = dim3(DIM);
        cfg.blockDim = dim3(256);
        cfg.attrs = &at;
        cfg.numAttrs = 1;
        if (cudaLaunchKernelEx(&cfg, build_a_kernel) != cudaSuccess)
            build_a_kernel<<<DIM, 256>>>();
    }
    {
        cudaLaunchConfig_t cfg = {};
        cfg.gridDim = dim3(batch / DIM);
        cfg.blockDim = dim3(256);
        cfg.dynamicSmemBytes = SMEM_BYTES;
        cfg.attrs = &at;
        cfg.numAttrs = 1;
        if (cudaLaunchKernelEx(&cfg, vqa_main, x, outp) != cudaSuccess)
            vqa_main<<<batch / DIM, 256, SMEM_BYTES>>>(x, outp);
    }
}